// round 11
// baseline (speedup 1.0000x reference)
#include <cuda_runtime.h>
#include <cuda.h>
#include <cuda_fp16.h>
#include <cstdint>

#define CIN 512
#define COUT 512
#define HH 64
#define WW 64
#define BB 8
#define SS 512

#define M_TILE 128
#define N_TILE 128             // 2 output rows x 64 cols
#define KC 64                  // halves per chunk -> 128B rows (SW128)
#define NTAPS 9
#define NCHUNK (NTAPS * (512 / KC))     // 72
#define NSS 3                           // super-stages (2 chunks each)
#define NSUPER (NCHUNK / 2)             // 36
#define A_BYTES (M_TILE * 128)          // 16KB
#define B_BYTES (N_TILE * 128)          // 16KB
#define STAGE_BYTES (A_BYTES + B_BYTES) // 32KB
#define SUPER_BYTES (2 * STAGE_BYTES)   // 64KB
#define SM_TILES 1024
#define SMEM_BYTES (SM_TILES + NSS * SUPER_BYTES)   // 197632

#define XP_ROW 514                      // xprep smem row stride (halves); odd word stride
#define XP_SMEM (66 * XP_ROW * 2)       // 67848 B

// ---------------------------------------------------------------------------
__device__ float  g_s[BB * CIN];
__device__ float  g_wsq[COUT * CIN];
__device__ float  g_demod[BB * COUT];
__device__ __half g_A[(size_t)NTAPS * COUT * CIN];      // fp16 weights (4.7MB)
__device__ __half g_X[(size_t)BB * 66 * 66 * CIN];      // fp16 padded mod x (36MB)

__device__ __forceinline__ uint32_t smem_u32(const void* p) {
    uint32_t a;
    asm("{ .reg .u64 t; cvta.to.shared.u64 t, %1; cvt.u32.u64 %0, t; }" : "=r"(a) : "l"(p));
    return a;
}
__device__ __forceinline__ void mbar_init(uint32_t m, uint32_t cnt) {
    asm volatile("mbarrier.init.shared.b64 [%0], %1;" :: "r"(m), "r"(cnt) : "memory");
}
__device__ __forceinline__ void mbar_arrive(uint32_t m) {
    asm volatile("mbarrier.arrive.shared.b64 _, [%0];" :: "r"(m) : "memory");
}
__device__ __forceinline__ void mbar_expect_tx(uint32_t m, uint32_t bytes) {
    asm volatile("mbarrier.arrive.expect_tx.shared.b64 _, [%0], %1;" :: "r"(m), "r"(bytes) : "memory");
}
__device__ __forceinline__ void mbar_wait(uint32_t m, uint32_t parity) {
    asm volatile(
        "{\n\t.reg .pred P;\n\t"
        "W_%=:\n\t"
        "mbarrier.try_wait.parity.acquire.cta.shared::cta.b64 P, [%0], %1, 0x989680;\n\t"
        "@P bra.uni D_%=;\n\t"
        "bra.uni W_%=;\n\t"
        "D_%=:\n\t}"
        :: "r"(m), "r"(parity) : "memory");
}
__device__ __forceinline__ void tma_load_3d(uint32_t dst, const void* map,
                                            int c0, int c1, int c2, uint32_t mbar) {
    asm volatile(
        "cp.async.bulk.tensor.3d.shared::cta.global.tile.mbarrier::complete_tx::bytes "
        "[%0], [%1, {%2, %3, %4}], [%5];"
        :: "r"(dst), "l"(map), "r"(c0), "r"(c1), "r"(c2), "r"(mbar) : "memory");
}
__device__ __forceinline__ void tma_load_4d(uint32_t dst, const void* map,
                                            int c0, int c1, int c2, int c3, uint32_t mbar) {
    asm volatile(
        "cp.async.bulk.tensor.4d.shared::cta.global.tile.mbarrier::complete_tx::bytes "
        "[%0], [%1, {%2, %3, %4, %5}], [%6];"
        :: "r"(dst), "l"(map), "r"(c0), "r"(c1), "r"(c2), "r"(c3), "r"(mbar) : "memory");
}
__device__ __forceinline__ void mma_f16(float* d, const uint32_t* a, uint32_t b0, uint32_t b1) {
    asm volatile(
        "mma.sync.aligned.m16n8k16.row.col.f32.f16.f16.f32 "
        "{%0,%1,%2,%3}, {%4,%5,%6,%7}, {%8,%9}, {%0,%1,%2,%3};"
        : "+f"(d[0]), "+f"(d[1]), "+f"(d[2]), "+f"(d[3])
        : "r"(a[0]), "r"(a[1]), "r"(a[2]), "r"(a[3]), "r"(b0), "r"(b1));
}
__device__ __forceinline__ void ldsm4(uint32_t* r, uint32_t addr) {
    asm volatile("ldmatrix.sync.aligned.m8n8.x4.shared.b16 {%0,%1,%2,%3}, [%4];"
        : "=r"(r[0]), "=r"(r[1]), "=r"(r[2]), "=r"(r[3]) : "r"(addr));
}

// ---------------------------------------------------------------------------
// prep kernel 1: mod (blocks 0..511) + wprep (blocks 512..1535)
// ---------------------------------------------------------------------------
__global__ void prep1_kernel(const float* __restrict__ style,
                             const float* __restrict__ w_mod,
                             const float* __restrict__ b_mod,
                             const float* __restrict__ weight) {
    if (blockIdx.x < 512) {
        int warp = (blockIdx.x * 256 + threadIdx.x) >> 5;
        int lane = threadIdx.x & 31;
        int b = warp >> 9, ci = warp & 511;
        const float* st = style + b * SS;
        const float* wm = w_mod + ci * SS;
        float sum = 0.f;
        #pragma unroll 4
        for (int j = lane; j < SS; j += 32) sum += st[j] * wm[j];
        #pragma unroll
        for (int o = 16; o; o >>= 1) sum += __shfl_xor_sync(0xffffffffu, sum, o);
        if (lane == 0) g_s[warp] = sum + b_mod[ci];
    } else {
        int idx = (blockIdx.x - 512) * 256 + threadIdx.x;   // 0..262143
        int co = idx >> 9, ci = idx & 511;
        const float* wp = weight + ((size_t)co * CIN + ci) * 9;
        float sq = 0.f;
        #pragma unroll
        for (int t = 0; t < 9; t++) {
            float v = wp[t];
            sq += v * v;
            g_A[((size_t)t * COUT + co) * CIN + ci] = __float2half(v);
        }
        g_wsq[co * CIN + ci] = sq;
    }
}

// ---------------------------------------------------------------------------
// prep kernel 2: demod (blocks 0..255) + xprep transpose (blocks 256..783)
// ---------------------------------------------------------------------------
__global__ void prep2_kernel(const float* __restrict__ x) {
    extern __shared__ __half sh[];     // [66][XP_ROW]
    if (blockIdx.x < 256) {
        int warp = (blockIdx.x * 512 + threadIdx.x) >> 5;
        int lane = threadIdx.x & 31;
        int b = warp >> 9, co = warp & 511;
        float sum = 0.f;
        #pragma unroll 4
        for (int j = lane; j < CIN; j += 32) {
            float sv = g_s[b * CIN + j];
            sum += sv * sv * g_wsq[co * CIN + j];
        }
        #pragma unroll
        for (int o = 16; o; o >>= 1) sum += __shfl_xor_sync(0xffffffffu, sum, o);
        if (lane == 0) g_demod[warp] = rsqrtf(sum + 1e-8f);
    } else {
        int blk = blockIdx.x - 256;       // 0..527
        int y = blk % 66, b = blk / 66;
        int tid = threadIdx.x;            // 512
        int wid = tid >> 5, lane = tid & 31;
        bool interior = (y >= 1 && y <= 64);
        // phase 1: coalesced reads of x rows; transpose into smem sh[xx][ci]
        #pragma unroll 1
        for (int r = 0; r < 32; r++) {
            int ci = r * 16 + wid;
            float sv = g_s[b * CIN + ci];
            float v0 = 0.f, v1 = 0.f;
            if (interior) {
                const float* xr = x + ((size_t)(b * CIN + ci) * HH + (y - 1)) * WW;
                v0 = xr[lane] * sv;
                v1 = xr[lane + 32] * sv;
            }
            sh[(1 + lane) * XP_ROW + ci]  = __float2half(v0);
            sh[(33 + lane) * XP_ROW + ci] = __float2half(v1);
            if (lane == 0) {
                sh[ci] = __half(0.f);                 // xx = 0
                sh[65 * XP_ROW + ci] = __half(0.f);   // xx = 65
            }
        }
        __syncthreads();
        // phase 2: 32-bit conflict-bounded smem reads packed into STG.128;
        // gmem writes fully linear (dst contiguous across xx)
        const uint32_t* shu = (const uint32_t*)sh;
        uint4* dst16 = (uint4*)(g_X + ((size_t)b * 66 + y) * 66 * CIN);
        #pragma unroll 2
        for (int i = tid; i < 66 * 64; i += 512) {
            int xx = i >> 6, c4 = (i & 63) * 4;
            const uint32_t* p = shu + xx * 257 + c4;
            uint4 v;
            v.x = p[0]; v.y = p[1]; v.z = p[2]; v.w = p[3];
            dst16[i] = v;
        }
    }
}

// ---------------------------------------------------------------------------
// GEMM: fp16 m16n8k16, TMA producer + 8 consumer warps (64co x 32px each).
// Paired-chunk super-stages: one mbarrier wait per 2 chunks (TRYWAIT amortize).
// ---------------------------------------------------------------------------
__global__ void __launch_bounds__(288, 1)
gemm_kernel(const __grid_constant__ CUtensorMap tmA,
            const __grid_constant__ CUtensorMap tmB,
            float* __restrict__ out) {
    extern __shared__ char smem[];
    uint32_t sb = smem_u32(smem);
    int tid = threadIdx.x;
    int wid = tid >> 5, lane = tid & 31;
    int tg = lane >> 2, tr = lane & 3;

    int pt = blockIdx.x;                 // 32 pixel tiles (2 rows x 64)
    int cobase = blockIdx.y * M_TILE;    // 4 co tiles
    int b = blockIdx.z;
    int y0 = pt * 2;

    uint32_t mb_full = sb;               // 3 x 8B
    uint32_t mb_cons = sb + 64;          // 3 x 8B

    if (tid == 0) {
        #pragma unroll
        for (int s = 0; s < NSS; s++) {
            mbar_init(mb_full + s * 8, 1);
            mbar_init(mb_cons + s * 8, 8);
        }
        asm volatile("fence.proxy.async.shared::cta;" ::: "memory");
    }
    __syncthreads();

    // ---- producer: warp 8, lane 0 ----
    if (wid == 8) {
        if (lane == 0) {
            int s = 0;
            int ws = 0, wph = 0;
            for (int sc = 0; sc < NSUPER; sc++) {
                if (sc >= NSS) {
                    mbar_wait(mb_cons + ws * 8, wph);
                    if (++ws == NSS) { ws = 0; wph ^= 1; }
                }
                uint32_t base = sb + SM_TILES + s * SUPER_BYTES;
                mbar_expect_tx(mb_full + s * 8, SUPER_BYTES);
                #pragma unroll
                for (int cc = 0; cc < 2; cc++) {
                    int c = sc * 2 + cc;
                    int tap = c >> 3, kc = c & 7, k0 = kc * KC;
                    int dy = tap / 3, dx = tap - dy * 3;
                    uint32_t smA = base + cc * STAGE_BYTES;
                    tma_load_3d(smA, &tmA, k0, cobase, tap, mb_full + s * 8);
                    tma_load_4d(smA + A_BYTES, &tmB, k0, dx, y0 + dy, b, mb_full + s * 8);
                }
                if (++s == NSS) s = 0;
            }
        }
        return;
    }

    // ---- consumers: warps 0..7, warp tile 64(co) x 32(px) ----
    int wm = wid >> 2, wn = wid & 3;
    int l7 = lane & 7;
    uint32_t swz = (uint32_t)l7 << 4;
    // A groups: (m0-7,k0)(m8-15,k0)(m0-7,k8)(m8-15,k8)
    uint32_t aRow = wm * 64 + l7 + ((lane & 8) ? 8 : 0);
    uint32_t aKoff = (lane & 16) ? 16u : 0u;
    // B groups: (n0-7,k0)(n0-7,k8)(n8-15,k0)(n8-15,k8)
    uint32_t bRow = wn * 32 + l7 + ((lane & 16) ? 8 : 0);
    uint32_t bKoff = (lane & 8) ? 16u : 0u;

    float acc[4][4][4];
    #pragma unroll
    for (int i = 0; i < 4; i++)
        #pragma unroll
        for (int j = 0; j < 4; j++)
            #pragma unroll
            for (int q = 0; q < 4; q++) acc[i][j][q] = 0.f;

    uint32_t fa[2][4][4], fb[2][2][4];

    int s = 0, ph = 0;
    for (int sc = 0; sc < NSUPER; sc++) {
        mbar_wait(mb_full + s * 8, ph);
        #pragma unroll
        for (int cc = 0; cc < 2; cc++) {
            uint32_t As = sb + SM_TILES + s * SUPER_BYTES + cc * STAGE_BYTES;
            uint32_t aBase = As + aRow * 128;
            uint32_t bBase = As + A_BYTES + bRow * 128;

            // slice 0 -> buffer 0
            {
                uint32_t aCol = aKoff ^ swz, bCol = bKoff ^ swz;
                #pragma unroll
                for (int i = 0; i < 4; i++) ldsm4(fa[0][i], aBase + i * 2048 + aCol);
                #pragma unroll
                for (int jp = 0; jp < 2; jp++) ldsm4(fb[0][jp], bBase + jp * 2048 + bCol);
            }

            #pragma unroll
            for (int ks = 0; ks < 4; ks++) {
                const int cur = ks & 1, nxt = cur ^ 1;
                if (ks < 3) {
                    uint32_t aCol = ((uint32_t)((ks + 1) * 32) + aKoff) ^ swz;
                    uint32_t bCol = ((uint32_t)((ks + 1) * 32) + bKoff) ^ swz;
                    #pragma unroll
                    for (int i = 0; i < 4; i++) ldsm4(fa[nxt][i], aBase + i * 2048 + aCol);
                    #pragma unroll
                    for (int jp = 0; jp < 2; jp++) ldsm4(fb[nxt][jp], bBase + jp * 2048 + bCol);
                } else if (cc == 1) {
                    // all smem reads of this super-stage issued -> release early
                    __syncwarp();
                    if (lane == 0) mbar_arrive(mb_cons + s * 8);
                }
                #pragma unroll
                for (int i = 0; i < 4; i++)
                    #pragma unroll
                    for (int j = 0; j < 4; j++)
                        mma_f16(acc[i][j], fa[cur][i],
                                fb[cur][j >> 1][(j & 1) * 2], fb[cur][j >> 1][(j & 1) * 2 + 1]);
            }
        }
        if (++s == NSS) { s = 0; ph ^= 1; }
    }

    // ---- epilogue: demod scale + float2 stores ----
    #pragma unroll
    for (int i = 0; i < 4; i++) {
        int co = cobase + wm * 64 + i * 16 + tg;
        float d0 = g_demod[b * COUT + co];
        float d1 = g_demod[b * COUT + co + 8];
        float* o0 = out + ((size_t)(b * COUT + co)) * (HH * WW) + pt * N_TILE;
        float* o1 = o0 + (size_t)8 * HH * WW;
        #pragma unroll
        for (int j = 0; j < 4; j++) {
            int p = wn * 32 + j * 8 + tr * 2;
            *(float2*)(o0 + p) = make_float2(acc[i][j][0] * d0, acc[i][j][1] * d0);
            *(float2*)(o1 + p) = make_float2(acc[i][j][2] * d1, acc[i][j][3] * d1);
        }
    }
}

// ---------------------------------------------------------------------------
extern "C" void kernel_launch(void* const* d_in, const int* in_sizes, int n_in,
                              void* d_out, int out_size) {
    const float* x      = (const float*)d_in[0];
    const float* style  = (const float*)d_in[1];
    const float* w_mod  = (const float*)d_in[2];
    const float* b_mod  = (const float*)d_in[3];
    const float* weight = (const float*)d_in[4];
    float* out = (float*)d_out;

    prep1_kernel<<<1536, 256>>>(style, w_mod, b_mod, weight);
    cudaFuncSetAttribute(prep2_kernel, cudaFuncAttributeMaxDynamicSharedMemorySize, XP_SMEM);
    prep2_kernel<<<784, 512, XP_SMEM>>>(x);

    // tensor maps (host-side, capture-safe)
    typedef CUresult (*EncFn)(CUtensorMap*, CUtensorMapDataType, cuuint32_t, void*,
                              const cuuint64_t*, const cuuint64_t*, const cuuint32_t*,
                              const cuuint32_t*, CUtensorMapInterleave, CUtensorMapSwizzle,
                              CUtensorMapL2promotion, CUtensorMapFloatOOBfill);
    EncFn enc = nullptr;
    cudaDriverEntryPointQueryResult qr;
    cudaGetDriverEntryPoint("cuTensorMapEncodeTiled", (void**)&enc, cudaEnableDefault, &qr);

    void* pA = nullptr; void* pX = nullptr;
    cudaGetSymbolAddress(&pA, g_A);
    cudaGetSymbolAddress(&pX, g_X);

    static CUtensorMap tmA, tmB;
    {
        cuuint64_t dims[3]    = {CIN, COUT, NTAPS};
        cuuint64_t strides[2] = {(cuuint64_t)CIN * 2, (cuuint64_t)COUT * CIN * 2};
        cuuint32_t box[3]     = {KC, M_TILE, 1};
        cuuint32_t es[3]      = {1, 1, 1};
        enc(&tmA, CU_TENSOR_MAP_DATA_TYPE_FLOAT16, 3, pA, dims, strides, box, es,
            CU_TENSOR_MAP_INTERLEAVE_NONE, CU_TENSOR_MAP_SWIZZLE_128B,
            CU_TENSOR_MAP_L2_PROMOTION_L2_128B, CU_TENSOR_MAP_FLOAT_OOB_FILL_NONE);
    }
    {
        cuuint64_t dims[4]    = {CIN, 66, 66, BB};
        cuuint64_t strides[3] = {(cuuint64_t)CIN * 2, 66ull * CIN * 2, 66ull * 66 * CIN * 2};
        cuuint32_t box[4]     = {KC, 64, 2, 1};
        cuuint32_t es[4]      = {1, 1, 1, 1};
        enc(&tmB, CU_TENSOR_MAP_DATA_TYPE_FLOAT16, 4, pX, dims, strides, box, es,
            CU_TENSOR_MAP_INTERLEAVE_NONE, CU_TENSOR_MAP_SWIZZLE_128B,
            CU_TENSOR_MAP_L2_PROMOTION_L2_128B, CU_TENSOR_MAP_FLOAT_OOB_FILL_NONE);
    }

    cudaFuncSetAttribute(gemm_kernel, cudaFuncAttributeMaxDynamicSharedMemorySize, SMEM_BYTES);
    gemm_kernel<<<dim3(32, COUT / M_TILE, BB), 288, SMEM_BYTES>>>(tmA, tmB, out);
}

// round 12
// speedup vs baseline: 1.3688x; 1.3688x over previous
#include <cuda_runtime.h>
#include <cuda.h>
#include <cuda_fp16.h>
#include <cstdint>

#define CIN 512
#define COUT 512
#define HH 64
#define WW 64
#define BB 8
#define SS 512

#define M_TILE 128
#define N_TILE 128             // 2 output rows x 64 cols
#define KC 64                  // halves per chunk -> 128B rows (SW128)
#define NTAPS 9
#define NCHUNK (NTAPS * (512 / KC))     // 72
#define NSTAGE 6
#define A_BYTES (M_TILE * 128)          // 16KB
#define B_BYTES (N_TILE * 128)          // 16KB
#define STAGE_BYTES (A_BYTES + B_BYTES) // 32KB
#define SM_TILES 1024
#define SMEM_BYTES (SM_TILES + NSTAGE * STAGE_BYTES)   // 197632

#define XP_ROW 514                      // xprep smem row stride (halves); odd word stride
#define XP_SMEM (66 * XP_ROW * 2)       // 67848 B

// ---------------------------------------------------------------------------
__device__ float  g_s[BB * CIN];
__device__ float  g_wsq[COUT * CIN];
__device__ float  g_demod[BB * COUT];
__device__ __half g_A[(size_t)NTAPS * COUT * CIN];      // fp16 weights (4.7MB)
__device__ __half g_X[(size_t)BB * 66 * 66 * CIN];      // fp16 padded mod x (36MB)

__device__ __forceinline__ uint32_t smem_u32(const void* p) {
    uint32_t a;
    asm("{ .reg .u64 t; cvta.to.shared.u64 t, %1; cvt.u32.u64 %0, t; }" : "=r"(a) : "l"(p));
    return a;
}
__device__ __forceinline__ void mbar_init(uint32_t m, uint32_t cnt) {
    asm volatile("mbarrier.init.shared.b64 [%0], %1;" :: "r"(m), "r"(cnt) : "memory");
}
__device__ __forceinline__ void mbar_arrive(uint32_t m) {
    asm volatile("mbarrier.arrive.shared.b64 _, [%0];" :: "r"(m) : "memory");
}
__device__ __forceinline__ void mbar_expect_tx(uint32_t m, uint32_t bytes) {
    asm volatile("mbarrier.arrive.expect_tx.shared.b64 _, [%0], %1;" :: "r"(m), "r"(bytes) : "memory");
}
__device__ __forceinline__ void mbar_wait(uint32_t m, uint32_t parity) {
    asm volatile(
        "{\n\t.reg .pred P;\n\t"
        "W_%=:\n\t"
        "mbarrier.try_wait.parity.acquire.cta.shared::cta.b64 P, [%0], %1, 0x989680;\n\t"
        "@P bra.uni D_%=;\n\t"
        "bra.uni W_%=;\n\t"
        "D_%=:\n\t}"
        :: "r"(m), "r"(parity) : "memory");
}
__device__ __forceinline__ void tma_load_3d(uint32_t dst, const void* map,
                                            int c0, int c1, int c2, uint32_t mbar) {
    asm volatile(
        "cp.async.bulk.tensor.3d.shared::cta.global.tile.mbarrier::complete_tx::bytes "
        "[%0], [%1, {%2, %3, %4}], [%5];"
        :: "r"(dst), "l"(map), "r"(c0), "r"(c1), "r"(c2), "r"(mbar) : "memory");
}
__device__ __forceinline__ void tma_load_4d(uint32_t dst, const void* map,
                                            int c0, int c1, int c2, int c3, uint32_t mbar) {
    asm volatile(
        "cp.async.bulk.tensor.4d.shared::cta.global.tile.mbarrier::complete_tx::bytes "
        "[%0], [%1, {%2, %3, %4, %5}], [%6];"
        :: "r"(dst), "l"(map), "r"(c0), "r"(c1), "r"(c2), "r"(c3), "r"(mbar) : "memory");
}
__device__ __forceinline__ void mma_f16(float* d, const uint32_t* a, uint32_t b0, uint32_t b1) {
    asm volatile(
        "mma.sync.aligned.m16n8k16.row.col.f32.f16.f16.f32 "
        "{%0,%1,%2,%3}, {%4,%5,%6,%7}, {%8,%9}, {%0,%1,%2,%3};"
        : "+f"(d[0]), "+f"(d[1]), "+f"(d[2]), "+f"(d[3])
        : "r"(a[0]), "r"(a[1]), "r"(a[2]), "r"(a[3]), "r"(b0), "r"(b1));
}
__device__ __forceinline__ void ldsm4(uint32_t* r, uint32_t addr) {
    asm volatile("ldmatrix.sync.aligned.m8n8.x4.shared.b16 {%0,%1,%2,%3}, [%4];"
        : "=r"(r[0]), "=r"(r[1]), "=r"(r[2]), "=r"(r[3]) : "r"(addr));
}

// ---------------------------------------------------------------------------
// prep kernel 1: mod (blocks 0..511) + wprep (blocks 512..1535)
// ---------------------------------------------------------------------------
__global__ void prep1_kernel(const float* __restrict__ style,
                             const float* __restrict__ w_mod,
                             const float* __restrict__ b_mod,
                             const float* __restrict__ weight) {
    if (blockIdx.x < 512) {
        int warp = (blockIdx.x * 256 + threadIdx.x) >> 5;
        int lane = threadIdx.x & 31;
        int b = warp >> 9, ci = warp & 511;
        const float* st = style + b * SS;
        const float* wm = w_mod + ci * SS;
        float sum = 0.f;
        #pragma unroll 4
        for (int j = lane; j < SS; j += 32) sum += st[j] * wm[j];
        #pragma unroll
        for (int o = 16; o; o >>= 1) sum += __shfl_xor_sync(0xffffffffu, sum, o);
        if (lane == 0) g_s[warp] = sum + b_mod[ci];
    } else {
        int idx = (blockIdx.x - 512) * 256 + threadIdx.x;   // 0..262143
        int co = idx >> 9, ci = idx & 511;
        const float* wp = weight + ((size_t)co * CIN + ci) * 9;
        float sq = 0.f;
        #pragma unroll
        for (int t = 0; t < 9; t++) {
            float v = wp[t];
            sq += v * v;
            g_A[((size_t)t * COUT + co) * CIN + ci] = __float2half(v);
        }
        g_wsq[co * CIN + ci] = sq;
    }
}

// ---------------------------------------------------------------------------
// prep kernel 2: demod (blocks 0..255) + xprep transpose (blocks 256..783)
// ---------------------------------------------------------------------------
__global__ void prep2_kernel(const float* __restrict__ x) {
    extern __shared__ __half sh[];     // [66][XP_ROW]
    if (blockIdx.x < 256) {
        int warp = (blockIdx.x * 512 + threadIdx.x) >> 5;
        int lane = threadIdx.x & 31;
        int b = warp >> 9, co = warp & 511;
        float sum = 0.f;
        #pragma unroll 4
        for (int j = lane; j < CIN; j += 32) {
            float sv = g_s[b * CIN + j];
            sum += sv * sv * g_wsq[co * CIN + j];
        }
        #pragma unroll
        for (int o = 16; o; o >>= 1) sum += __shfl_xor_sync(0xffffffffu, sum, o);
        if (lane == 0) g_demod[warp] = rsqrtf(sum + 1e-8f);
    } else {
        int blk = blockIdx.x - 256;       // 0..527
        int y = blk % 66, b = blk / 66;
        int tid = threadIdx.x;            // 512
        int wid = tid >> 5, lane = tid & 31;
        bool interior = (y >= 1 && y <= 64);
        // phase 1: coalesced reads of x rows; transpose into smem sh[xx][ci]
        #pragma unroll 1
        for (int r = 0; r < 32; r++) {
            int ci = r * 16 + wid;
            float sv = g_s[b * CIN + ci];
            float v0 = 0.f, v1 = 0.f;
            if (interior) {
                const float* xr = x + ((size_t)(b * CIN + ci) * HH + (y - 1)) * WW;
                v0 = xr[lane] * sv;
                v1 = xr[lane + 32] * sv;
            }
            sh[(1 + lane) * XP_ROW + ci]  = __float2half(v0);
            sh[(33 + lane) * XP_ROW + ci] = __float2half(v1);
            if (lane == 0) {
                sh[ci] = __half(0.f);                 // xx = 0
                sh[65 * XP_ROW + ci] = __half(0.f);   // xx = 65
            }
        }
        __syncthreads();
        // phase 2: 32-bit smem reads packed into STG.128; linear gmem writes
        const uint32_t* shu = (const uint32_t*)sh;
        uint4* dst16 = (uint4*)(g_X + ((size_t)b * 66 + y) * 66 * CIN);
        #pragma unroll 2
        for (int i = tid; i < 66 * 64; i += 512) {
            int xx = i >> 6, c4 = (i & 63) * 4;
            const uint32_t* p = shu + xx * 257 + c4;
            uint4 v;
            v.x = p[0]; v.y = p[1]; v.z = p[2]; v.w = p[3];
            dst16[i] = v;
        }
    }
}

// ---------------------------------------------------------------------------
// GEMM: fp16 m16n8k16, TMA producer + 8 consumer warps (64co x 32px each).
// R10 structure: 6 per-chunk 32KB stages, fragment ping-pong within chunk.
// ---------------------------------------------------------------------------
__global__ void __launch_bounds__(288, 1)
gemm_kernel(const __grid_constant__ CUtensorMap tmA,
            const __grid_constant__ CUtensorMap tmB,
            float* __restrict__ out) {
    extern __shared__ char smem[];
    uint32_t sb = smem_u32(smem);
    int tid = threadIdx.x;
    int wid = tid >> 5, lane = tid & 31;
    int tg = lane >> 2, tr = lane & 3;

    int pt = blockIdx.x;                 // 32 pixel tiles (2 rows x 64)
    int cobase = blockIdx.y * M_TILE;    // 4 co tiles
    int b = blockIdx.z;
    int y0 = pt * 2;

    uint32_t mb_full = sb;               // 6 x 8B
    uint32_t mb_cons = sb + 64;          // 6 x 8B

    if (tid == 0) {
        #pragma unroll
        for (int s = 0; s < NSTAGE; s++) {
            mbar_init(mb_full + s * 8, 1);
            mbar_init(mb_cons + s * 8, 8);
        }
        asm volatile("fence.proxy.async.shared::cta;" ::: "memory");
    }
    __syncthreads();

    // ---- producer: warp 8, lane 0 ----
    if (wid == 8) {
        if (lane == 0) {
            int s = 0;
            int ws = 0, wph = 0;
            for (int c = 0; c < NCHUNK; c++) {
                if (c >= NSTAGE) {
                    mbar_wait(mb_cons + ws * 8, wph);
                    if (++ws == NSTAGE) { ws = 0; wph ^= 1; }
                }
                int tap = c >> 3, kc = c & 7, k0 = kc * KC;
                int dy = tap / 3, dx = tap - dy * 3;
                uint32_t smA = sb + SM_TILES + s * STAGE_BYTES;
                uint32_t smB = smA + A_BYTES;
                mbar_expect_tx(mb_full + s * 8, STAGE_BYTES);
                tma_load_3d(smA, &tmA, k0, cobase, tap, mb_full + s * 8);
                tma_load_4d(smB, &tmB, k0, dx, y0 + dy, b, mb_full + s * 8);
                if (++s == NSTAGE) s = 0;
            }
        }
        return;
    }

    // ---- consumers: warps 0..7, warp tile 64(co) x 32(px) ----
    int wm = wid >> 2, wn = wid & 3;
    int l7 = lane & 7;
    uint32_t swz = (uint32_t)l7 << 4;
    // A groups: (m0-7,k0)(m8-15,k0)(m0-7,k8)(m8-15,k8)
    uint32_t aRow = wm * 64 + l7 + ((lane & 8) ? 8 : 0);
    uint32_t aKoff = (lane & 16) ? 16u : 0u;
    // B groups: (n0-7,k0)(n0-7,k8)(n8-15,k0)(n8-15,k8)
    uint32_t bRow = wn * 32 + l7 + ((lane & 16) ? 8 : 0);
    uint32_t bKoff = (lane & 8) ? 16u : 0u;

    float acc[4][4][4];
    #pragma unroll
    for (int i = 0; i < 4; i++)
        #pragma unroll
        for (int j = 0; j < 4; j++)
            #pragma unroll
            for (int q = 0; q < 4; q++) acc[i][j][q] = 0.f;

    uint32_t fa[2][4][4], fb[2][2][4];

    int s = 0, ph = 0;
    for (int c = 0; c < NCHUNK; c++) {
        mbar_wait(mb_full + s * 8, ph);
        uint32_t As = sb + SM_TILES + s * STAGE_BYTES;
        uint32_t aBase = As + aRow * 128;
        uint32_t bBase = As + A_BYTES + bRow * 128;

        // slice 0 -> buffer 0
        {
            uint32_t aCol = aKoff ^ swz, bCol = bKoff ^ swz;
            #pragma unroll
            for (int i = 0; i < 4; i++) ldsm4(fa[0][i], aBase + i * 2048 + aCol);
            #pragma unroll
            for (int jp = 0; jp < 2; jp++) ldsm4(fb[0][jp], bBase + jp * 2048 + bCol);
        }

        #pragma unroll
        for (int ks = 0; ks < 4; ks++) {
            const int cur = ks & 1, nxt = cur ^ 1;
            if (ks < 3) {
                uint32_t aCol = ((uint32_t)((ks + 1) * 32) + aKoff) ^ swz;
                uint32_t bCol = ((uint32_t)((ks + 1) * 32) + bKoff) ^ swz;
                #pragma unroll
                for (int i = 0; i < 4; i++) ldsm4(fa[nxt][i], aBase + i * 2048 + aCol);
                #pragma unroll
                for (int jp = 0; jp < 2; jp++) ldsm4(fb[nxt][jp], bBase + jp * 2048 + bCol);
            } else {
                // all smem reads of this chunk issued -> release stage early
                __syncwarp();
                if (lane == 0) mbar_arrive(mb_cons + s * 8);
            }
            #pragma unroll
            for (int i = 0; i < 4; i++)
                #pragma unroll
                for (int j = 0; j < 4; j++)
                    mma_f16(acc[i][j], fa[cur][i],
                            fb[cur][j >> 1][(j & 1) * 2], fb[cur][j >> 1][(j & 1) * 2 + 1]);
        }
        if (++s == NSTAGE) { s = 0; ph ^= 1; }
    }

    // ---- epilogue: demod scale + float2 stores ----
    #pragma unroll
    for (int i = 0; i < 4; i++) {
        int co = cobase + wm * 64 + i * 16 + tg;
        float d0 = g_demod[b * COUT + co];
        float d1 = g_demod[b * COUT + co + 8];
        float* o0 = out + ((size_t)(b * COUT + co)) * (HH * WW) + pt * N_TILE;
        float* o1 = o0 + (size_t)8 * HH * WW;
        #pragma unroll
        for (int j = 0; j < 4; j++) {
            int p = wn * 32 + j * 8 + tr * 2;
            *(float2*)(o0 + p) = make_float2(acc[i][j][0] * d0, acc[i][j][1] * d0);
            *(float2*)(o1 + p) = make_float2(acc[i][j][2] * d1, acc[i][j][3] * d1);
        }
    }
}

// ---------------------------------------------------------------------------
extern "C" void kernel_launch(void* const* d_in, const int* in_sizes, int n_in,
                              void* d_out, int out_size) {
    const float* x      = (const float*)d_in[0];
    const float* style  = (const float*)d_in[1];
    const float* w_mod  = (const float*)d_in[2];
    const float* b_mod  = (const float*)d_in[3];
    const float* weight = (const float*)d_in[4];
    float* out = (float*)d_out;

    prep1_kernel<<<1536, 256>>>(style, w_mod, b_mod, weight);
    cudaFuncSetAttribute(prep2_kernel, cudaFuncAttributeMaxDynamicSharedMemorySize, XP_SMEM);
    prep2_kernel<<<784, 512, XP_SMEM>>>(x);

    // tensor maps (host-side, capture-safe)
    typedef CUresult (*EncFn)(CUtensorMap*, CUtensorMapDataType, cuuint32_t, void*,
                              const cuuint64_t*, const cuuint64_t*, const cuuint32_t*,
                              const cuuint32_t*, CUtensorMapInterleave, CUtensorMapSwizzle,
                              CUtensorMapL2promotion, CUtensorMapFloatOOBfill);
    EncFn enc = nullptr;
    cudaDriverEntryPointQueryResult qr;
    cudaGetDriverEntryPoint("cuTensorMapEncodeTiled", (void**)&enc, cudaEnableDefault, &qr);

    void* pA = nullptr; void* pX = nullptr;
    cudaGetSymbolAddress(&pA, g_A);
    cudaGetSymbolAddress(&pX, g_X);

    static CUtensorMap tmA, tmB;
    {
        cuuint64_t dims[3]    = {CIN, COUT, NTAPS};
        cuuint64_t strides[2] = {(cuuint64_t)CIN * 2, (cuuint64_t)COUT * CIN * 2};
        cuuint32_t box[3]     = {KC, M_TILE, 1};
        cuuint32_t es[3]      = {1, 1, 1};
        enc(&tmA, CU_TENSOR_MAP_DATA_TYPE_FLOAT16, 3, pA, dims, strides, box, es,
            CU_TENSOR_MAP_INTERLEAVE_NONE, CU_TENSOR_MAP_SWIZZLE_128B,
            CU_TENSOR_MAP_L2_PROMOTION_L2_128B, CU_TENSOR_MAP_FLOAT_OOB_FILL_NONE);
    }
    {
        cuuint64_t dims[4]    = {CIN, 66, 66, BB};
        cuuint64_t strides[3] = {(cuuint64_t)CIN * 2, 66ull * CIN * 2, 66ull * 66 * CIN * 2};
        cuuint32_t box[4]     = {KC, 64, 2, 1};
        cuuint32_t es[4]      = {1, 1, 1, 1};
        enc(&tmB, CU_TENSOR_MAP_DATA_TYPE_FLOAT16, 4, pX, dims, strides, box, es,
            CU_TENSOR_MAP_INTERLEAVE_NONE, CU_TENSOR_MAP_SWIZZLE_128B,
            CU_TENSOR_MAP_L2_PROMOTION_L2_128B, CU_TENSOR_MAP_FLOAT_OOB_FILL_NONE);
    }

    cudaFuncSetAttribute(gemm_kernel, cudaFuncAttributeMaxDynamicSharedMemorySize, SMEM_BYTES);
    gemm_kernel<<<dim3(32, COUT / M_TILE, BB), 288, SMEM_BYTES>>>(tmA, tmB, out);
}

// round 13
// speedup vs baseline: 1.4952x; 1.0923x over previous
#include <cuda_runtime.h>
#include <cuda.h>
#include <cuda_fp16.h>
#include <cstdint>

#define CIN 512
#define COUT 512
#define HH 64
#define WW 64
#define BB 8
#define SS 512

#define M_TILE 128
#define N_TILE 128             // 2 output rows x 64 cols
#define KC 64                  // halves per chunk -> 128B rows (SW128)
#define NTAPS 9
#define NCHUNK (NTAPS * (512 / KC))     // 72
#define NSTAGE 6
#define A_BYTES (M_TILE * 128)          // 16KB
#define B_BYTES (N_TILE * 128)          // 16KB
#define STAGE_BYTES (A_BYTES + B_BYTES) // 32KB
#define SM_TILES 1024
#define SMEM_BYTES (SM_TILES + NSTAGE * STAGE_BYTES)   // 197632

#define XP_ROW 514                      // xprep smem row stride (halves); odd word stride
#define XP_SMEM (66 * XP_ROW * 2)       // 67848 B

// ---------------------------------------------------------------------------
__device__ float  g_s[BB * CIN];
__device__ float  g_wsq[COUT * CIN];
__device__ float  g_demod[BB * COUT];
__device__ __half g_A[(size_t)NTAPS * COUT * CIN];      // fp16 weights (4.7MB)
__device__ __half g_X[(size_t)BB * 66 * 66 * CIN];      // fp16 padded mod x (36MB)

__device__ __forceinline__ uint32_t smem_u32(const void* p) {
    uint32_t a;
    asm("{ .reg .u64 t; cvta.to.shared.u64 t, %1; cvt.u32.u64 %0, t; }" : "=r"(a) : "l"(p));
    return a;
}
__device__ __forceinline__ void mbar_init(uint32_t m, uint32_t cnt) {
    asm volatile("mbarrier.init.shared.b64 [%0], %1;" :: "r"(m), "r"(cnt) : "memory");
}
__device__ __forceinline__ void mbar_arrive(uint32_t m) {
    asm volatile("mbarrier.arrive.shared.b64 _, [%0];" :: "r"(m) : "memory");
}
__device__ __forceinline__ void mbar_expect_tx(uint32_t m, uint32_t bytes) {
    asm volatile("mbarrier.arrive.expect_tx.shared.b64 _, [%0], %1;" :: "r"(m), "r"(bytes) : "memory");
}
__device__ __forceinline__ void mbar_wait(uint32_t m, uint32_t parity) {
    asm volatile(
        "{\n\t.reg .pred P;\n\t"
        "W_%=:\n\t"
        "mbarrier.try_wait.parity.acquire.cta.shared::cta.b64 P, [%0], %1, 0x989680;\n\t"
        "@P bra.uni D_%=;\n\t"
        "bra.uni W_%=;\n\t"
        "D_%=:\n\t}"
        :: "r"(m), "r"(parity) : "memory");
}
__device__ __forceinline__ void tma_load_3d(uint32_t dst, const void* map,
                                            int c0, int c1, int c2, uint32_t mbar) {
    asm volatile(
        "cp.async.bulk.tensor.3d.shared::cta.global.tile.mbarrier::complete_tx::bytes "
        "[%0], [%1, {%2, %3, %4}], [%5];"
        :: "r"(dst), "l"(map), "r"(c0), "r"(c1), "r"(c2), "r"(mbar) : "memory");
}
__device__ __forceinline__ void tma_load_4d(uint32_t dst, const void* map,
                                            int c0, int c1, int c2, int c3, uint32_t mbar) {
    asm volatile(
        "cp.async.bulk.tensor.4d.shared::cta.global.tile.mbarrier::complete_tx::bytes "
        "[%0], [%1, {%2, %3, %4, %5}], [%6];"
        :: "r"(dst), "l"(map), "r"(c0), "r"(c1), "r"(c2), "r"(c3), "r"(mbar) : "memory");
}
__device__ __forceinline__ void mma_f16(float* d, const uint32_t* a, uint32_t b0, uint32_t b1) {
    asm volatile(
        "mma.sync.aligned.m16n8k16.row.col.f32.f16.f16.f32 "
        "{%0,%1,%2,%3}, {%4,%5,%6,%7}, {%8,%9}, {%0,%1,%2,%3};"
        : "+f"(d[0]), "+f"(d[1]), "+f"(d[2]), "+f"(d[3])
        : "r"(a[0]), "r"(a[1]), "r"(a[2]), "r"(a[3]), "r"(b0), "r"(b1));
}
__device__ __forceinline__ void ldsm4(uint32_t* r, uint32_t addr) {
    asm volatile("ldmatrix.sync.aligned.m8n8.x4.shared.b16 {%0,%1,%2,%3}, [%4];"
        : "=r"(r[0]), "=r"(r[1]), "=r"(r[2]), "=r"(r[3]) : "r"(addr));
}

// ---------------------------------------------------------------------------
// prep kernel 1: mod (blocks 0..511) + wprep (blocks 512..1535)
// ---------------------------------------------------------------------------
__global__ void prep1_kernel(const float* __restrict__ style,
                             const float* __restrict__ w_mod,
                             const float* __restrict__ b_mod,
                             const float* __restrict__ weight) {
    if (blockIdx.x < 512) {
        int warp = (blockIdx.x * 256 + threadIdx.x) >> 5;
        int lane = threadIdx.x & 31;
        int b = warp >> 9, ci = warp & 511;
        const float* st = style + b * SS;
        const float* wm = w_mod + ci * SS;
        float sum = 0.f;
        #pragma unroll 4
        for (int j = lane; j < SS; j += 32) sum += st[j] * wm[j];
        #pragma unroll
        for (int o = 16; o; o >>= 1) sum += __shfl_xor_sync(0xffffffffu, sum, o);
        if (lane == 0) g_s[warp] = sum + b_mod[ci];
    } else {
        int idx = (blockIdx.x - 512) * 256 + threadIdx.x;   // 0..262143
        int co = idx >> 9, ci = idx & 511;
        const float* wp = weight + ((size_t)co * CIN + ci) * 9;
        float sq = 0.f;
        #pragma unroll
        for (int t = 0; t < 9; t++) {
            float v = wp[t];
            sq += v * v;
            g_A[((size_t)t * COUT + co) * CIN + ci] = __float2half(v);
        }
        g_wsq[co * CIN + ci] = sq;
    }
}

// ---------------------------------------------------------------------------
// prep kernel 2: demod (blocks 0..255) + xprep transpose (blocks 256..783)
// ---------------------------------------------------------------------------
__global__ void prep2_kernel(const float* __restrict__ x) {
    extern __shared__ __half sh[];     // [66][XP_ROW]
    if (blockIdx.x < 256) {
        int warp = (blockIdx.x * 512 + threadIdx.x) >> 5;
        int lane = threadIdx.x & 31;
        int b = warp >> 9, co = warp & 511;
        float sum = 0.f;
        #pragma unroll 4
        for (int j = lane; j < CIN; j += 32) {
            float sv = g_s[b * CIN + j];
            sum += sv * sv * g_wsq[co * CIN + j];
        }
        #pragma unroll
        for (int o = 16; o; o >>= 1) sum += __shfl_xor_sync(0xffffffffu, sum, o);
        if (lane == 0) g_demod[warp] = rsqrtf(sum + 1e-8f);
    } else {
        int blk = blockIdx.x - 256;       // 0..527
        int y = blk % 66, b = blk / 66;
        int tid = threadIdx.x;            // 512
        int wid = tid >> 5, lane = tid & 31;
        bool interior = (y >= 1 && y <= 64);
        // phase 1: coalesced reads of x rows; transpose into smem sh[xx][ci]
        #pragma unroll 1
        for (int r = 0; r < 32; r++) {
            int ci = r * 16 + wid;
            float sv = g_s[b * CIN + ci];
            float v0 = 0.f, v1 = 0.f;
            if (interior) {
                const float* xr = x + ((size_t)(b * CIN + ci) * HH + (y - 1)) * WW;
                v0 = xr[lane] * sv;
                v1 = xr[lane + 32] * sv;
            }
            sh[(1 + lane) * XP_ROW + ci]  = __float2half(v0);
            sh[(33 + lane) * XP_ROW + ci] = __float2half(v1);
            if (lane == 0) {
                sh[ci] = __half(0.f);                 // xx = 0
                sh[65 * XP_ROW + ci] = __half(0.f);   // xx = 65
            }
        }
        __syncthreads();
        // phase 2: 32-bit smem reads packed into STG.128; linear gmem writes
        const uint32_t* shu = (const uint32_t*)sh;
        uint4* dst16 = (uint4*)(g_X + ((size_t)b * 66 + y) * 66 * CIN);
        #pragma unroll 2
        for (int i = tid; i < 66 * 64; i += 512) {
            int xx = i >> 6, c4 = (i & 63) * 4;
            const uint32_t* p = shu + xx * 257 + c4;
            uint4 v;
            v.x = p[0]; v.y = p[1]; v.z = p[2]; v.w = p[3];
            dst16[i] = v;
        }
    }
}

// ---------------------------------------------------------------------------
// GEMM: fp16 m16n8k16, TMA producer + 8 consumer warps (64co x 32px each).
// R10 structure: 6 per-chunk 32KB stages, fragment ping-pong within chunk.
// Demod prefetched before mainloop; producer uses packed tap LUT.
// ---------------------------------------------------------------------------
__global__ void __launch_bounds__(288, 1)
gemm_kernel(const __grid_constant__ CUtensorMap tmA,
            const __grid_constant__ CUtensorMap tmB,
            float* __restrict__ out) {
    extern __shared__ char smem[];
    uint32_t sb = smem_u32(smem);
    int tid = threadIdx.x;
    int wid = tid >> 5, lane = tid & 31;
    int tg = lane >> 2, tr = lane & 3;

    int pt = blockIdx.x;                 // 32 pixel tiles (2 rows x 64)
    int cobase = blockIdx.y * M_TILE;    // 4 co tiles
    int b = blockIdx.z;
    int y0 = pt * 2;

    uint32_t mb_full = sb;               // 6 x 8B
    uint32_t mb_cons = sb + 64;          // 6 x 8B

    if (tid == 0) {
        #pragma unroll
        for (int s = 0; s < NSTAGE; s++) {
            mbar_init(mb_full + s * 8, 1);
            mbar_init(mb_cons + s * 8, 8);
        }
        asm volatile("fence.proxy.async.shared::cta;" ::: "memory");
    }
    __syncthreads();

    // ---- producer: warp 8, lane 0 ----
    if (wid == 8) {
        if (lane == 0) {
            // packed LUT: bits[0:4]=dy, [4:8]=dx per tap
            const uint32_t tapLUT[NTAPS] =
                {0x00,0x10,0x20, 0x01,0x11,0x21, 0x02,0x12,0x22};
            int s = 0;
            int ws = 0, wph = 0;
            for (int c = 0; c < NCHUNK; c++) {
                if (c >= NSTAGE) {
                    mbar_wait(mb_cons + ws * 8, wph);
                    if (++ws == NSTAGE) { ws = 0; wph ^= 1; }
                }
                int tap = c >> 3, k0 = (c & 7) * KC;
                uint32_t t = tapLUT[tap];
                int dy = t & 15, dx = t >> 4;
                uint32_t smA = sb + SM_TILES + s * STAGE_BYTES;
                uint32_t smB = smA + A_BYTES;
                mbar_expect_tx(mb_full + s * 8, STAGE_BYTES);
                tma_load_3d(smA, &tmA, k0, cobase, tap, mb_full + s * 8);
                tma_load_4d(smB, &tmB, k0, dx, y0 + dy, b, mb_full + s * 8);
                if (++s == NSTAGE) s = 0;
            }
        }
        return;
    }

    // ---- consumers: warps 0..7, warp tile 64(co) x 32(px) ----
    int wm = wid >> 2, wn = wid & 3;
    int l7 = lane & 7;
    uint32_t swz = (uint32_t)l7 << 4;
    // A groups: (m0-7,k0)(m8-15,k0)(m0-7,k8)(m8-15,k8)
    uint32_t aRow = wm * 64 + l7 + ((lane & 8) ? 8 : 0);
    uint32_t aKoff = (lane & 16) ? 16u : 0u;
    // B groups: (n0-7,k0)(n0-7,k8)(n8-15,k0)(n8-15,k8)
    uint32_t bRow = wn * 32 + l7 + ((lane & 16) ? 8 : 0);
    uint32_t bKoff = (lane & 8) ? 16u : 0u;

    // prefetch demod scales (independent of mainloop; hides DRAM/L2 latency)
    float dsc[4][2];
    #pragma unroll
    for (int i = 0; i < 4; i++) {
        int co = cobase + wm * 64 + i * 16 + tg;
        dsc[i][0] = __ldg(&g_demod[b * COUT + co]);
        dsc[i][1] = __ldg(&g_demod[b * COUT + co + 8]);
    }

    float acc[4][4][4];
    #pragma unroll
    for (int i = 0; i < 4; i++)
        #pragma unroll
        for (int j = 0; j < 4; j++)
            #pragma unroll
            for (int q = 0; q < 4; q++) acc[i][j][q] = 0.f;

    uint32_t fa[2][4][4], fb[2][2][4];

    int s = 0, ph = 0;
    for (int c = 0; c < NCHUNK; c++) {
        mbar_wait(mb_full + s * 8, ph);
        uint32_t As = sb + SM_TILES + s * STAGE_BYTES;
        uint32_t aBase = As + aRow * 128;
        uint32_t bBase = As + A_BYTES + bRow * 128;

        // slice 0 -> buffer 0
        {
            uint32_t aCol = aKoff ^ swz, bCol = bKoff ^ swz;
            #pragma unroll
            for (int i = 0; i < 4; i++) ldsm4(fa[0][i], aBase + i * 2048 + aCol);
            #pragma unroll
            for (int jp = 0; jp < 2; jp++) ldsm4(fb[0][jp], bBase + jp * 2048 + bCol);
        }

        #pragma unroll
        for (int ks = 0; ks < 4; ks++) {
            const int cur = ks & 1, nxt = cur ^ 1;
            if (ks < 3) {
                uint32_t aCol = ((uint32_t)((ks + 1) * 32) + aKoff) ^ swz;
                uint32_t bCol = ((uint32_t)((ks + 1) * 32) + bKoff) ^ swz;
                #pragma unroll
                for (int i = 0; i < 4; i++) ldsm4(fa[nxt][i], aBase + i * 2048 + aCol);
                #pragma unroll
                for (int jp = 0; jp < 2; jp++) ldsm4(fb[nxt][jp], bBase + jp * 2048 + bCol);
            } else {
                // all smem reads of this chunk issued -> release stage early
                __syncwarp();
                if (lane == 0) mbar_arrive(mb_cons + s * 8);
            }
            #pragma unroll
            for (int i = 0; i < 4; i++)
                #pragma unroll
                for (int j = 0; j < 4; j++)
                    mma_f16(acc[i][j], fa[cur][i],
                            fb[cur][j >> 1][(j & 1) * 2], fb[cur][j >> 1][(j & 1) * 2 + 1]);
        }
        if (++s == NSTAGE) { s = 0; ph ^= 1; }
    }

    // ---- epilogue: demod scale + float2 stores ----
    #pragma unroll
    for (int i = 0; i < 4; i++) {
        int co = cobase + wm * 64 + i * 16 + tg;
        float d0 = dsc[i][0];
        float d1 = dsc[i][1];
        float* o0 = out + ((size_t)(b * COUT + co)) * (HH * WW) + pt * N_TILE;
        float* o1 = o0 + (size_t)8 * HH * WW;
        #pragma unroll
        for (int j = 0; j < 4; j++) {
            int p = wn * 32 + j * 8 + tr * 2;
            *(float2*)(o0 + p) = make_float2(acc[i][j][0] * d0, acc[i][j][1] * d0);
            *(float2*)(o1 + p) = make_float2(acc[i][j][2] * d1, acc[i][j][3] * d1);
        }
    }
}

// ---------------------------------------------------------------------------
extern "C" void kernel_launch(void* const* d_in, const int* in_sizes, int n_in,
                              void* d_out, int out_size) {
    const float* x      = (const float*)d_in[0];
    const float* style  = (const float*)d_in[1];
    const float* w_mod  = (const float*)d_in[2];
    const float* b_mod  = (const float*)d_in[3];
    const float* weight = (const float*)d_in[4];
    float* out = (float*)d_out;

    prep1_kernel<<<1536, 256>>>(style, w_mod, b_mod, weight);
    cudaFuncSetAttribute(prep2_kernel, cudaFuncAttributeMaxDynamicSharedMemorySize, XP_SMEM);
    prep2_kernel<<<784, 512, XP_SMEM>>>(x);

    // tensor maps (host-side, capture-safe)
    typedef CUresult (*EncFn)(CUtensorMap*, CUtensorMapDataType, cuuint32_t, void*,
                              const cuuint64_t*, const cuuint64_t*, const cuuint32_t*,
                              const cuuint32_t*, CUtensorMapInterleave, CUtensorMapSwizzle,
                              CUtensorMapL2promotion, CUtensorMapFloatOOBfill);
    EncFn enc = nullptr;
    cudaDriverEntryPointQueryResult qr;
    cudaGetDriverEntryPoint("cuTensorMapEncodeTiled", (void**)&enc, cudaEnableDefault, &qr);

    void* pA = nullptr; void* pX = nullptr;
    cudaGetSymbolAddress(&pA, g_A);
    cudaGetSymbolAddress(&pX, g_X);

    static CUtensorMap tmA, tmB;
    {
        cuuint64_t dims[3]    = {CIN, COUT, NTAPS};
        cuuint64_t strides[2] = {(cuuint64_t)CIN * 2, (cuuint64_t)COUT * CIN * 2};
        cuuint32_t box[3]     = {KC, M_TILE, 1};
        cuuint32_t es[3]      = {1, 1, 1};
        enc(&tmA, CU_TENSOR_MAP_DATA_TYPE_FLOAT16, 3, pA, dims, strides, box, es,
            CU_TENSOR_MAP_INTERLEAVE_NONE, CU_TENSOR_MAP_SWIZZLE_128B,
            CU_TENSOR_MAP_L2_PROMOTION_L2_128B, CU_TENSOR_MAP_FLOAT_OOB_FILL_NONE);
    }
    {
        cuuint64_t dims[4]    = {CIN, 66, 66, BB};
        cuuint64_t strides[3] = {(cuuint64_t)CIN * 2, 66ull * CIN * 2, 66ull * 66 * CIN * 2};
        cuuint32_t box[4]     = {KC, 64, 2, 1};
        cuuint32_t es[4]      = {1, 1, 1, 1};
        enc(&tmB, CU_TENSOR_MAP_DATA_TYPE_FLOAT16, 4, pX, dims, strides, box, es,
            CU_TENSOR_MAP_INTERLEAVE_NONE, CU_TENSOR_MAP_SWIZZLE_128B,
            CU_TENSOR_MAP_L2_PROMOTION_L2_128B, CU_TENSOR_MAP_FLOAT_OOB_FILL_NONE);
    }

    cudaFuncSetAttribute(gemm_kernel, cudaFuncAttributeMaxDynamicSharedMemorySize, SMEM_BYTES);
    gemm_kernel<<<dim3(32, COUT / M_TILE, BB), 288, SMEM_BYTES>>>(tmA, tmB, out);
}